// round 5
// baseline (speedup 1.0000x reference)
#include <cuda_runtime.h>

#define T_SEQ 2048
#define I_IN 7
#define H_DIM 64
#define G_DIM 256   // 4*H
#define B_SZ 256
#define O_DIM 3

using u64 = unsigned long long;

// ---------- packed f32x2 helpers (Blackwell FFMA2 path) ----------
__device__ __forceinline__ u64 pack2(float lo, float hi) {
    u64 r;
    asm("mov.b64 %0, {%1, %2};" : "=l"(r) : "f"(lo), "f"(hi));
    return r;
}
__device__ __forceinline__ void unpack2(u64 v, float& lo, float& hi) {
    asm("mov.b64 {%0, %1}, %2;" : "=f"(lo), "=f"(hi) : "l"(v));
}
__device__ __forceinline__ void ffma2(u64& acc, u64 a, u64 b) {
    asm("fma.rn.f32x2 %0, %1, %2, %0;" : "+l"(acc) : "l"(a), "l"(b));
}

// ---------- activations (MUFU.EX2/RCP based, ~2^-22 accurate) ----------
__device__ __forceinline__ float sigm(float x) {
    return __fdividef(1.0f, 1.0f + __expf(-x));
}
__device__ __forceinline__ float tanh_acc(float x) {
    return 1.0f - __fdividef(2.0f, __expf(2.0f * x) + 1.0f);
}

// Forward final hidden state, written by kernel1 and read by kernel2.
__device__ float g_hF[B_SZ * H_DIM];

// ---------- shared memory (dynamic), one batch element per CTA ----------
struct Smem {
    float xs[T_SEQ][8];    // xs[t][i], i<7 valid, [7] zero pad.   65536 B
    float hs[2][H_DIM];    // ping-pong h state.                     512 B
};                         // total 66048 B -> 2 CTAs/SM

__global__ void __launch_bounds__(256, 2)
lstm_fwd_kernel(const float* __restrict__ x,
                const float* __restrict__ W_ih,
                const float* __restrict__ W_hh,
                const float* __restrict__ b_ih,
                const float* __restrict__ b_hh) {
    extern __shared__ Smem sh[];
    Smem& s = sh[0];

    const int tid = threadIdx.x;
    const int b = blockIdx.x;
    const int w = tid >> 5;
    const int l = tid & 31;
    const int gate = l >> 3;          // 0=i, 1=f, 2=g, 3=o
    const int unit = w * 8 + (l & 7); // hidden unit 0..63
    const int row = gate * H_DIM + unit;

    // ---- stage this batch element's x into smem ----
    {
        const float* xb = x + (size_t)b * T_SEQ * I_IN;
        for (int idx = tid; idx < T_SEQ * I_IN; idx += 256) {
            int t = idx / I_IN;
            int i = idx - t * I_IN;
            s.xs[t][i] = xb[idx];
        }
        for (int t = tid; t < T_SEQ; t += 256) s.xs[t][7] = 0.f;
        if (tid < 2 * H_DIM) ((float*)s.hs)[tid] = 0.f;
    }

    // ---- per-lane weights in registers (lane owns W row `row`) ----
    u64 Wk[32];   // W_hh[row,:] packed along k as f32x2 pairs
    {
        const ulonglong2* wp = reinterpret_cast<const ulonglong2*>(W_hh + row * H_DIM);
#pragma unroll
        for (int q = 0; q < 16; q++) {
            ulonglong2 v = wp[q];
            Wk[2 * q] = v.x;
            Wk[2 * q + 1] = v.y;
        }
    }
    u64 Wi[4];    // W_ih[row,:] packed along i (pad i=7 with 0)
    {
        float wv[8];
#pragma unroll
        for (int i = 0; i < 7; i++) wv[i] = W_ih[row * I_IN + i];
        wv[7] = 0.f;
#pragma unroll
        for (int q = 0; q < 4; q++) Wi[q] = pack2(wv[2 * q], wv[2 * q + 1]);
    }
    const float bias = b_ih[row] + b_hh[row];
    // branch-free activation: tanh(z) = 2*sigm(2z)-1
    const float zscale = (gate == 2) ? 2.f : 1.f;

    float c_state = 0.f;

    __syncthreads();

    // input projection + bias for timestep t (packed along i)
    auto iproj = [&](int t) -> float {
        u64 acc = 0ull;
        const ulonglong2* xp = reinterpret_cast<const ulonglong2*>(s.xs[t]);
        ulonglong2 v0 = xp[0], v1 = xp[1];
        ffma2(acc, Wi[0], v0.x);
        ffma2(acc, Wi[1], v0.y);
        ffma2(acc, Wi[2], v1.x);
        ffma2(acc, Wi[3], v1.y);
        float lo, hi;
        unpack2(acc, lo, hi);
        return (lo + hi) + bias;
    };

    float accX = iproj(0);

    for (int t = 0; t < T_SEQ; t++) {
        // ---- recurrent dot: z = accX + W_hh[row,:] . h  (read buffer t&1) ----
        u64 a0 = 0ull, a1 = 0ull;
        const ulonglong2* hp = reinterpret_cast<const ulonglong2*>(s.hs[t & 1]);
#pragma unroll
        for (int q = 0; q < 8; q++) {
            ulonglong2 v0 = hp[2 * q];
            ffma2(a0, Wk[4 * q], v0.x);
            ffma2(a0, Wk[4 * q + 1], v0.y);
            ulonglong2 v1 = hp[2 * q + 1];
            ffma2(a1, Wk[4 * q + 2], v1.x);
            ffma2(a1, Wk[4 * q + 3], v1.y);
        }
        float l0, h0, l1, h1;
        unpack2(a0, l0, h0);
        unpack2(a1, l1, h1);
        float z = accX + ((l0 + h0) + (l1 + h1));

        // ---- per-lane activation (no smem round-trip) ----
        float sg = sigm(zscale * z);
        float a = zscale * sg - (zscale - 1.f);   // sigm for i/f/o, tanh for g

        // ---- intra-warp gather of (i,f,g,o) for this lane's unit ----
        float p = __shfl_xor_sync(0xFFFFFFFFu, a, 8);
        float lo = (l & 8) ? p : a;    // lower gate of the xor-8 pair
        float hi = (l & 8) ? a : p;    // upper gate
        float q0 = __shfl_xor_sync(0xFFFFFFFFu, lo, 16);
        float q1 = __shfl_xor_sync(0xFFFFFFFFu, hi, 16);
        float ig = (l & 16) ? q0 : lo;
        float fg = (l & 16) ? q1 : hi;
        float gg = (l & 16) ? lo : q0;
        float og = (l & 16) ? hi : q1;

        // ---- cell update (redundant in 4 lanes per unit, consistent) ----
        c_state = fg * c_state + ig * gg;
        float hval = og * tanh_acc(c_state);
        if (gate == 0) s.hs[(t + 1) & 1][unit] = hval;   // write buffer (t+1)&1

        if (t + 1 < T_SEQ) accX = iproj(t + 1);

        __syncthreads();   // one barrier per step (ping-pong removes WAR hazard)
    }

    // final h is in buffer T_SEQ & 1 == 0
    if (tid < H_DIM) g_hF[b * H_DIM + tid] = s.hs[0][tid];
}

// One backward LSTM step (from zero state on x[:,T-1,:]) + final linear.
__global__ void __launch_bounds__(256)
lstm_bwd_out_kernel(const float* __restrict__ x,
                    const float* __restrict__ W_ih_b,
                    const float* __restrict__ b_ih_b,
                    const float* __restrict__ b_hh_b,
                    const float* __restrict__ W_lin,
                    const float* __restrict__ b_lin,
                    float* __restrict__ out) {
    __shared__ float zs[G_DIM];
    __shared__ float hb[H_DIM];
    const int b = blockIdx.x;
    const int g = threadIdx.x;

    const float* xt = x + ((size_t)b * T_SEQ + (T_SEQ - 1)) * I_IN;
    float z = b_ih_b[g] + b_hh_b[g];
#pragma unroll
    for (int i = 0; i < I_IN; i++) z += W_ih_b[g * I_IN + i] * xt[i];
    zs[g] = z;
    __syncthreads();

    if (g < H_DIM) {
        float ig = sigm(zs[g]);
        float gg = tanh_acc(zs[2 * H_DIM + g]);
        float og = sigm(zs[3 * H_DIM + g]);
        float c = ig * gg;              // f * c_prev = 0 at first step
        hb[g] = og * tanh_acc(c);
    }
    __syncthreads();

    if (g < O_DIM) {
        float acc = b_lin[g];
        const float* wrow = W_lin + g * (2 * H_DIM);
        const float* hf = g_hF + b * H_DIM;
#pragma unroll 8
        for (int j = 0; j < H_DIM; j++) acc += wrow[j] * hf[j];
#pragma unroll 8
        for (int j = 0; j < H_DIM; j++) acc += wrow[H_DIM + j] * hb[j];
        out[b * O_DIM + g] = acc;
    }
}

extern "C" void kernel_launch(void* const* d_in, const int* in_sizes, int n_in,
                              void* d_out, int out_size) {
    const float* x      = (const float*)d_in[0];
    const float* Wih_f  = (const float*)d_in[1];
    const float* Whh_f  = (const float*)d_in[2];
    const float* bih_f  = (const float*)d_in[3];
    const float* bhh_f  = (const float*)d_in[4];
    const float* Wih_b  = (const float*)d_in[5];
    const float* bih_b  = (const float*)d_in[7];
    const float* bhh_b  = (const float*)d_in[8];
    const float* Wlin   = (const float*)d_in[9];
    const float* blin   = (const float*)d_in[10];
    float* out = (float*)d_out;

    cudaFuncSetAttribute(lstm_fwd_kernel,
                         cudaFuncAttributeMaxDynamicSharedMemorySize,
                         (int)sizeof(Smem));

    lstm_fwd_kernel<<<B_SZ, 256, sizeof(Smem)>>>(x, Wih_f, Whh_f, bih_f, bhh_f);
    lstm_bwd_out_kernel<<<B_SZ, 256>>>(x, Wih_b, bih_b, bhh_b, Wlin, blin, out);
}

// round 8
// speedup vs baseline: 1.1448x; 1.1448x over previous
#include <cuda_runtime.h>

#define T_SEQ 2048
#define I_IN 7
#define H_DIM 64
#define G_DIM 256   // 4*H
#define B_SZ 256
#define O_DIM 3

using u64 = unsigned long long;

#define BAR_SYNC(id)   asm volatile("bar.sync %0, 256;"   :: "r"(id) : "memory")
#define BAR_ARRIVE(id) asm volatile("bar.arrive %0, 256;" :: "r"(id) : "memory")

// ---------- packed f32x2 helpers (Blackwell FFMA2 path) ----------
__device__ __forceinline__ u64 pack2(float lo, float hi) {
    u64 r;
    asm("mov.b64 %0, {%1, %2};" : "=l"(r) : "f"(lo), "f"(hi));
    return r;
}
__device__ __forceinline__ void unpack2(u64 v, float& lo, float& hi) {
    asm("mov.b64 {%0, %1}, %2;" : "=f"(lo), "=f"(hi) : "l"(v));
}
__device__ __forceinline__ void ffma2(u64& acc, u64 a, u64 b) {
    asm("fma.rn.f32x2 %0, %1, %2, %0;" : "+l"(acc) : "l"(a), "l"(b));
}
__device__ __forceinline__ u64 add2(u64 a, u64 b) {
    u64 r;
    asm("add.rn.f32x2 %0, %1, %2;" : "=l"(r) : "l"(a), "l"(b));
    return r;
}

// ---------- activations ----------
__device__ __forceinline__ float sigm(float x) {           // accurate (~2^-22)
    return __fdividef(1.0f, 1.0f + __expf(-x));
}
__device__ __forceinline__ float tanh_fast(float x) {      // MUFU.TANH (~1e-4)
    float r;
    asm("tanh.approx.f32 %0, %1;" : "=f"(r) : "f"(x));
    return r;
}

// Forward final hidden state, written by kernel1 and read by kernel2.
__device__ float g_hF[B_SZ * H_DIM];

// ---------- shared memory (dynamic), one batch element per CTA ----------
struct Smem {
    float xs[T_SEQ][8];     // xs[t][i], i<7 valid, [7] zero pad.   65536 B
    float hs[2][H_DIM];     // ping-pong h state.                     512 B
    float zs[G_DIM];        // pre-activation gates.                 1024 B
    float axs[2][H_DIM];    // ping-pong accX for combiner rows.      512 B
};                          // total 67584 B -> 2 CTAs/SM

__global__ void __launch_bounds__(256, 2)
lstm_fwd_kernel(const float* __restrict__ x,
                const float* __restrict__ W_ih,
                const float* __restrict__ W_hh,
                const float* __restrict__ b_ih,
                const float* __restrict__ b_hh) {
    extern __shared__ Smem sh[];
    Smem& s = sh[0];

    const int tid = threadIdx.x;
    const int b = blockIdx.x;
    const int row = tid;                 // gate-row 0..255 owned by this thread
    const bool is_comb = (tid < H_DIM);  // warps 0-1: combiners (also units 0..63)
    const bool is_help = (tid >= 64 && tid < 128);  // warps 2-3: iproj helpers

    // ---- stage this batch element's x into smem ----
    {
        const float* xb = x + (size_t)b * T_SEQ * I_IN;
        for (int idx = tid; idx < T_SEQ * I_IN; idx += 256) {
            int t = idx / I_IN;
            int i = idx - t * I_IN;
            s.xs[t][i] = xb[idx];
        }
        for (int t = tid; t < T_SEQ; t += 256) s.xs[t][7] = 0.f;
        if (tid < 2 * H_DIM) ((float*)s.hs)[tid] = 0.f;
    }

    // ---- per-thread weights in registers ----
    u64 Wk[32];   // W_hh[row,:] packed along k as f32x2 pairs
    {
        const ulonglong2* wp = reinterpret_cast<const ulonglong2*>(W_hh + row * H_DIM);
#pragma unroll
        for (int q = 0; q < 16; q++) {
            ulonglong2 v = wp[q];
            Wk[2 * q] = v.x;
            Wk[2 * q + 1] = v.y;
        }
    }
    u64 Wi[4];    // W_ih[row,:] packed along i (pad i=7 with 0)
    {
        float wv[8];
#pragma unroll
        for (int i = 0; i < 7; i++) wv[i] = W_ih[row * I_IN + i];
        wv[7] = 0.f;
#pragma unroll
        for (int q = 0; q < 4; q++) Wi[q] = pack2(wv[2 * q], wv[2 * q + 1]);
    }
    const float bias = b_ih[row] + b_hh[row];

    // helper warps 2-3 also own the iproj for combiner row (tid-64) = 0..63
    u64 Wi2[4];
    float bias2 = 0.f;
    if (is_help) {
        const int r2 = tid - 64;
        float wv[8];
#pragma unroll
        for (int i = 0; i < 7; i++) wv[i] = W_ih[r2 * I_IN + i];
        wv[7] = 0.f;
#pragma unroll
        for (int q = 0; q < 4; q++) Wi2[q] = pack2(wv[2 * q], wv[2 * q + 1]);
        bias2 = b_ih[r2] + b_hh[r2];
    }

    float c_state = 0.f;

    __syncthreads();

    // input projection (packed along i); caller adds bias
    auto iproj = [&](int t, const u64* W) -> float {
        u64 acc = 0ull;
        const ulonglong2* xp = reinterpret_cast<const ulonglong2*>(s.xs[t]);
        ulonglong2 v0 = xp[0], v1 = xp[1];
        ffma2(acc, W[0], v0.x);
        ffma2(acc, W[1], v0.y);
        ffma2(acc, W[2], v1.x);
        ffma2(acc, W[3], v1.y);
        float lo, hi;
        unpack2(acc, lo, hi);
        return lo + hi;
    };

    float accX = iproj(0, Wi) + bias;   // everyone (combiners use it only at t=0)

    for (int t = 0; t < T_SEQ; t++) {
        // ---- recurrent dot: 4 accumulators, read h buffer t&1 ----
        u64 a0 = 0ull, a1 = 0ull, a2 = 0ull, a3 = 0ull;
        const ulonglong2* hp = reinterpret_cast<const ulonglong2*>(s.hs[t & 1]);
#pragma unroll
        for (int q = 0; q < 4; q++) {
            ulonglong2 v0 = hp[4 * q + 0];
            ulonglong2 v1 = hp[4 * q + 1];
            ulonglong2 v2 = hp[4 * q + 2];
            ulonglong2 v3 = hp[4 * q + 3];
            ffma2(a0, Wk[8 * q + 0], v0.x);
            ffma2(a0, Wk[8 * q + 1], v0.y);
            ffma2(a1, Wk[8 * q + 2], v1.x);
            ffma2(a1, Wk[8 * q + 3], v1.y);
            ffma2(a2, Wk[8 * q + 4], v2.x);
            ffma2(a2, Wk[8 * q + 5], v2.y);
            ffma2(a3, Wk[8 * q + 6], v3.x);
            ffma2(a3, Wk[8 * q + 7], v3.y);
        }
        float axv;
        if (is_comb) {
            axv = (t == 0) ? accX : s.axs[t & 1][tid];   // helper-provided accX
        } else {
            axv = accX;                                   // own register
        }
        u64 sum01 = add2(a0, a1);
        u64 sum23 = add2(a2, a3);
        u64 sum = add2(sum01, sum23);
        float lo, hi;
        unpack2(sum, lo, hi);
        s.zs[row] = axv + (lo + hi);

        if (!is_comb) {
            // ---- producers: publish z, then prep next-step input projections ----
            BAR_ARRIVE(1);
            int tn = (t + 1 < T_SEQ) ? (t + 1) : t;       // clamp (last iter unused)
            accX = iproj(tn, Wi) + bias;
            if (is_help) {
                s.axs[(t + 1) & 1][tid - 64] = iproj(tn, Wi2) + bias2;
            }
            BAR_SYNC(2);
        } else {
            // ---- combiners: gate math for unit = tid ----
            BAR_SYNC(1);
            float zi = s.zs[tid];
            float zf = s.zs[H_DIM + tid];
            float zg = s.zs[2 * H_DIM + tid];
            float zo = s.zs[3 * H_DIM + tid];
            float ig = sigm(zi);
            float fg = sigm(zf);
            float gg = tanh_fast(zg);
            float og = sigm(zo);
            c_state = fg * c_state + ig * gg;
            s.hs[(t + 1) & 1][tid] = og * tanh_fast(c_state);
            BAR_SYNC(2);
        }
    }

    // final h is in buffer T_SEQ & 1 == 0
    if (tid < H_DIM) g_hF[b * H_DIM + tid] = s.hs[0][tid];
}

// One backward LSTM step (from zero state on x[:,T-1,:]) + final linear.
__global__ void __launch_bounds__(256)
lstm_bwd_out_kernel(const float* __restrict__ x,
                    const float* __restrict__ W_ih_b,
                    const float* __restrict__ b_ih_b,
                    const float* __restrict__ b_hh_b,
                    const float* __restrict__ W_lin,
                    const float* __restrict__ b_lin,
                    float* __restrict__ out) {
    __shared__ float zs[G_DIM];
    __shared__ float hb[H_DIM];
    const int b = blockIdx.x;
    const int g = threadIdx.x;

    const float* xt = x + ((size_t)b * T_SEQ + (T_SEQ - 1)) * I_IN;
    float z = b_ih_b[g] + b_hh_b[g];
#pragma unroll
    for (int i = 0; i < I_IN; i++) z += W_ih_b[g * I_IN + i] * xt[i];
    zs[g] = z;
    __syncthreads();

    if (g < H_DIM) {
        float ig = sigm(zs[g]);
        float gg = tanhf(zs[2 * H_DIM + g]);
        float og = sigm(zs[3 * H_DIM + g]);
        float c = ig * gg;              // f * c_prev = 0 at first step
        hb[g] = og * tanhf(c);
    }
    __syncthreads();

    if (g < O_DIM) {
        float acc = b_lin[g];
        const float* wrow = W_lin + g * (2 * H_DIM);
        const float* hf = g_hF + b * H_DIM;
#pragma unroll 8
        for (int j = 0; j < H_DIM; j++) acc += wrow[j] * hf[j];
#pragma unroll 8
        for (int j = 0; j < H_DIM; j++) acc += wrow[H_DIM + j] * hb[j];
        out[b * O_DIM + g] = acc;
    }
}

extern "C" void kernel_launch(void* const* d_in, const int* in_sizes, int n_in,
                              void* d_out, int out_size) {
    const float* x      = (const float*)d_in[0];
    const float* Wih_f  = (const float*)d_in[1];
    const float* Whh_f  = (const float*)d_in[2];
    const float* bih_f  = (const float*)d_in[3];
    const float* bhh_f  = (const float*)d_in[4];
    const float* Wih_b  = (const float*)d_in[5];
    const float* bih_b  = (const float*)d_in[7];
    const float* bhh_b  = (const float*)d_in[8];
    const float* Wlin   = (const float*)d_in[9];
    const float* blin   = (const float*)d_in[10];
    float* out = (float*)d_out;

    cudaFuncSetAttribute(lstm_fwd_kernel,
                         cudaFuncAttributeMaxDynamicSharedMemorySize,
                         (int)sizeof(Smem));

    lstm_fwd_kernel<<<B_SZ, 256, sizeof(Smem)>>>(x, Wih_f, Whh_f, bih_f, bhh_f);
    lstm_bwd_out_kernel<<<B_SZ, 256>>>(x, Wih_b, bih_b, bhh_b, Wlin, blin, out);
}